// round 9
// baseline (speedup 1.0000x reference)
#include <cuda_runtime.h>
#include <mma.h>
#include <math.h>
#include <cstdint>

using namespace nvcuda;

#define BATCH 256
#define DIN   512
#define TSEQ  512
#define HID   1024
#define NG    4096
#define KTOT  1536
#define NCLS  1000

#define NBLK   128        // persistent blocks (<=148 SMs), 32 gate-cols each
#define NB     32
#define KSLICE 192        // k range owned by each of 8 warps
#define NKS    (KSLICE / 8)   // 24 k-steps per warp
#define SLAB   16         // batch rows per slab
#define NSLAB  (BATCH / SLAB) // 16

#define ALD    1540       // A slab row stride in floats (6160 B, 16B-aligned, %32==4)
#define ABUF_B (SLAB * ALD * 4)           // 98,560 B per buffer
#define OFF_A0 0
#define OFF_A1 ABUF_B
#define OFF_CP (2 * ABUF_B)               // 197,120: 8 warps x 16x32 partials
#define CP_B   (8 * SLAB * NB * 4)        // 16,384
#define OFF_BIAS (OFF_CP + CP_B)          // 213,504
#define SMEM_BYTES (OFF_BIAS + 128)       // 213,632  (< 227 KB limit)

// ---------------- static device scratch ----------------
__device__ float g_xT[(size_t)TSEQ * BATCH * DIN];   // x transposed [T][B][D], tf32-rounded
__device__ float g_W[(size_t)KTOT * NG];             // [Wh; Wx] gate-interleaved, tf32-rounded
__device__ float g_bias[NG];
__device__ float g_h[2][(size_t)BATCH * HID];        // double-buffered hidden state
__device__ float g_c[(size_t)BATCH * HID];           // cell state
__device__ unsigned g_arrive;
__device__ unsigned g_release;

__device__ __forceinline__ float rtf32(float v) {
    uint32_t u;
    asm("cvt.rna.tf32.f32 %0, %1;" : "=r"(u) : "f"(v));
    return __uint_as_float(u);
}
__device__ __forceinline__ unsigned ld_acquire(const unsigned* p) {
    unsigned v;
    asm volatile("ld.acquire.gpu.global.u32 %0, [%1];" : "=r"(v) : "l"(p));
    return v;
}
__device__ __forceinline__ void st_release(unsigned* p, unsigned v) {
    asm volatile("st.release.gpu.global.u32 [%0], %1;" :: "l"(p), "r"(v));
}
__device__ __forceinline__ void cp16(uint32_t dst, const float* src) {
    asm volatile("cp.async.cg.shared.global [%0], [%1], 16;\n" :: "r"(dst), "l"(src));
}
__device__ __forceinline__ void cp_commit() {
    asm volatile("cp.async.commit_group;\n");
}
template <int N>
__device__ __forceinline__ void cp_wait() {
    asm volatile("cp.async.wait_group %0;\n" :: "n"(N));
}

// ---------------- init ----------------
__global__ void init_kernel() {
    size_t i = blockIdx.x * (size_t)blockDim.x + threadIdx.x;
    if (i < (size_t)BATCH * HID) {
        g_h[0][i] = 0.0f;
        g_c[i]    = 0.0f;
    }
    if (i == 0) { g_arrive = 0u; g_release = 0u; }
}

// ---------------- pack weights: g_W[k][u*4+gate], gates (g,f,i,o), tf32-rounded ----------------
__global__ void pack_kernel(const float* __restrict__ Wfx, const float* __restrict__ Wfh,
                            const float* __restrict__ Wgx, const float* __restrict__ Wgh,
                            const float* __restrict__ Wix, const float* __restrict__ Wih,
                            const float* __restrict__ Wox, const float* __restrict__ Woh,
                            const float* __restrict__ bf,  const float* __restrict__ bg,
                            const float* __restrict__ bi,  const float* __restrict__ bo) {
    size_t idx = blockIdx.x * (size_t)blockDim.x + threadIdx.x;
    size_t total = (size_t)KTOT * NG;
    if (idx >= total) return;
    int e = (int)(idx % NG);
    int k = (int)(idx / NG);
    int u = e >> 2;
    int gate = e & 3;
    float v;
    if (k < HID) {
        const float* W = (gate == 0) ? Wgh : (gate == 1) ? Wfh : (gate == 2) ? Wih : Woh;
        v = W[(size_t)k * HID + u];
    } else {
        int d = k - HID;
        const float* W = (gate == 0) ? Wgx : (gate == 1) ? Wfx : (gate == 2) ? Wix : Wox;
        v = W[(size_t)d * HID + u];
    }
    g_W[idx] = rtf32(v);
    if (idx < NG) {
        const float* b = (gate == 0) ? bg : (gate == 1) ? bf : (gate == 2) ? bi : bo;
        g_bias[e] = b[u];
    }
}

// ---------------- transpose x [B,D,T] -> xT [T][B*D], tf32-rounded ----------------
__global__ void transpose_kernel(const float* __restrict__ x) {
    __shared__ float tile[32][33];
    int t0 = blockIdx.x * 32;
    int r0 = blockIdx.y * 32;
    int tx = threadIdx.x;
    int ty = threadIdx.y;     // blockDim = (32, 8)
#pragma unroll
    for (int i = 0; i < 32; i += 8)
        tile[ty + i][tx] = x[(size_t)(r0 + ty + i) * TSEQ + (t0 + tx)];
    __syncthreads();
#pragma unroll
    for (int i = 0; i < 32; i += 8)
        g_xT[(size_t)(t0 + ty + i) * (BATCH * DIN) + (r0 + tx)] = rtf32(tile[tx][ty + i]);
}

// ================= persistent LSTM kernel, B-in-registers =================
// 128 blocks x 256 threads (8 warps). Block owns gate-cols n0..n0+31. Warp w
// owns k-slice [192w, 192w+192): its 24x2 B fragments are loaded from g_W once
// and stay in registers for all 512 steps. Per step the 256 batch rows are
// processed in 16 slabs of 16: stage A slab (cp.async, double-buffered,
// overlapped with MMA), per-warp partial MMA, cross-warp reduce in SMEM,
// fused gate/cell epilogue. Grid softbarrier between timesteps.
__global__ void __launch_bounds__(256, 1) lstm_persistent_kernel() {
    extern __shared__ float smem[];
    float* sA[2] = { smem + OFF_A0 / 4, smem + OFF_A1 / 4 };
    float* sCp   = smem + OFF_CP / 4;
    float* sBias = smem + OFF_BIAS / 4;

    const int tid  = threadIdx.x;
    const int warp = tid >> 5;
    const int n0   = blockIdx.x * NB;
    const int u0   = n0 >> 2;
    const int kbase = warp * KSLICE;

    uint32_t sbase;
    {
        void* p = (void*)smem;
        asm("{ .reg .u64 tt; cvta.to.shared.u64 tt, %1; cvt.u32.u64 %0, tt; }"
            : "=r"(sbase) : "l"(p));
    }

    // ---- one-time: B fragments into registers (per-warp k-slice) ----
    wmma::fragment<wmma::matrix_b, 16, 16, 8, wmma::precision::tf32, wmma::row_major> bfr[NKS][2];
#pragma unroll
    for (int s = 0; s < NKS; ++s) {
#pragma unroll
        for (int b = 0; b < 2; ++b)
            wmma::load_matrix_sync(bfr[s][b],
                                   g_W + (size_t)(kbase + s * 8) * NG + n0 + b * 16, NG);
    }
    if (tid < NB) sBias[tid] = g_bias[n0 + tid];

    // epilogue constants (threads 0..127 handle one (row,unit) cell per slab)
    const int er = tid >> 3;     // slab-local row 0..15
    const int eu = tid & 7;      // unit 0..7
    __syncthreads();

    for (int t = 0; t < TSEQ; ++t) {
        const float* __restrict__ hin  = g_h[t & 1];
        float*       __restrict__ hout = g_h[(t + 1) & 1];
        const float* __restrict__ xTt  = g_xT + (size_t)t * (BATCH * DIN);

        // stage A slab: 16 rows x 1536 k, 24 cp16 per thread
        auto stageA = [&](int buf, int slab) {
            const int m0 = slab * SLAB;
            uint32_t dst0 = sbase + (buf ? OFF_A1 : OFF_A0);
#pragma unroll
            for (int j = 0; j < 24; ++j) {
                int idx = j * 256 + tid;          // 6144 float4
                int row = idx / 384;
                int q   = idx - row * 384;
                int k0  = q * 4;
                const float* src = (k0 < HID)
                    ? hin + (size_t)(m0 + row) * HID + k0
                    : xTt + (size_t)(m0 + row) * DIN + (k0 - HID);
                cp16(dst0 + (uint32_t)(row * ALD + k0) * 4u, src);
            }
            cp_commit();
        };

        stageA(0, 0);

        for (int slab = 0; slab < NSLAB; ++slab) {
            const int cur = slab & 1;
            cp_wait<0>();
            __syncthreads();                      // slab data visible; sCp free for reuse
            if (slab + 1 < NSLAB) stageA(cur ^ 1, slab + 1);   // overlap with MMA below

            // ---- per-warp partial MMA over its k-slice ----
            wmma::fragment<wmma::accumulator, 16, 16, 8, float> acc[2];
            wmma::fill_fragment(acc[0], 0.0f);
            wmma::fill_fragment(acc[1], 0.0f);
            const float* cA = sA[cur] + kbase;
#pragma unroll
            for (int s = 0; s < NKS; ++s) {
                wmma::fragment<wmma::matrix_a, 16, 16, 8, wmma::precision::tf32, wmma::row_major> af;
                wmma::load_matrix_sync(af, cA + s * 8, ALD);
                wmma::mma_sync(acc[0], af, bfr[s][0], acc[0]);
                wmma::mma_sync(acc[1], af, bfr[s][1], acc[1]);
            }
            wmma::store_matrix_sync(sCp + warp * (SLAB * NB),      acc[0], NB, wmma::mem_row_major);
            wmma::store_matrix_sync(sCp + warp * (SLAB * NB) + 16, acc[1], NB, wmma::mem_row_major);
            __syncthreads();

            // ---- reduce partials + fused cell update (threads 0..127) ----
            if (tid < 128) {
                float pg = 0.f, pf = 0.f, pi = 0.f, po = 0.f;
#pragma unroll
                for (int w = 0; w < 8; ++w) {
                    const float* p = sCp + w * (SLAB * NB) + er * NB + eu * 4;
                    pg += p[0]; pf += p[1]; pi += p[2]; po += p[3];
                }
                float gg = tanhf(pg + sBias[eu * 4 + 0]);
                float ff = tanhf(pf + sBias[eu * 4 + 1]);
                float ii = tanhf(pi + sBias[eu * 4 + 2]);
                float oo = tanhf(po + sBias[eu * 4 + 3]);
                size_t cidx = (size_t)(slab * SLAB + er) * HID + (u0 + eu);
                float c = gg * ii + g_c[cidx] * ff;
                g_c[cidx]  = c;
                hout[cidx] = rtf32(tanhf(c) * oo);
            }
        }

        // ---- grid softbarrier ----
        __threadfence();
        __syncthreads();
        if (tid == 0) {
            unsigned cnt    = atomicAdd(&g_arrive, 1u) + 1u;
            unsigned target = (unsigned)NBLK * (unsigned)(t + 1);
            if (cnt == target) {
                __threadfence();
                st_release(&g_release, (unsigned)(t + 1));
            } else {
                while (ld_acquire(&g_release) < (unsigned)(t + 1)) { }
            }
        }
        __syncthreads();
    }
}

// ---------------- head: softmax(h @ W_ph + b_p) ----------------
__global__ void __launch_bounds__(256) head_kernel(const float* __restrict__ Wph,
                                                   const float* __restrict__ bp,
                                                   float* __restrict__ out) {
    __shared__ float hs[HID];
    __shared__ float lg[NCLS];
    __shared__ float red[256];
    int b   = blockIdx.x;
    int tid = threadIdx.x;
    const float* h = g_h[0];   // after 512 steps, final h lives in buffer 0

    for (int i = tid; i < HID; i += 256)
        hs[i] = h[(size_t)b * HID + i];
    __syncthreads();

    for (int c = tid; c < NCLS; c += 256) {
        float acc = bp[c];
#pragma unroll 8
        for (int k = 0; k < HID; ++k)
            acc += hs[k] * Wph[(size_t)k * NCLS + c];
        lg[c] = acc;
    }
    __syncthreads();

    float m = -1e30f;
    for (int c = tid; c < NCLS; c += 256) m = fmaxf(m, lg[c]);
    red[tid] = m;
    __syncthreads();
    for (int s = 128; s > 0; s >>= 1) {
        if (tid < s) red[tid] = fmaxf(red[tid], red[tid + s]);
        __syncthreads();
    }
    m = red[0];
    __syncthreads();

    float sum = 0.0f;
    for (int c = tid; c < NCLS; c += 256) {
        float ex = expf(lg[c] - m);
        lg[c] = ex;
        sum += ex;
    }
    red[tid] = sum;
    __syncthreads();
    for (int s = 128; s > 0; s >>= 1) {
        if (tid < s) red[tid] += red[tid + s];
        __syncthreads();
    }
    float inv = 1.0f / red[0];
    for (int c = tid; c < NCLS; c += 256)
        out[(size_t)b * NCLS + c] = lg[c] * inv;
}

// ---------------- launch ----------------
extern "C" void kernel_launch(void* const* d_in, const int* in_sizes, int n_in,
                              void* d_out, int out_size) {
    (void)in_sizes; (void)n_in; (void)out_size;
    const float* x   = (const float*)d_in[0];
    const float* Wfx = (const float*)d_in[1];
    const float* Wfh = (const float*)d_in[2];
    const float* Wgx = (const float*)d_in[3];
    const float* Wgh = (const float*)d_in[4];
    const float* Wix = (const float*)d_in[5];
    const float* Wih = (const float*)d_in[6];
    const float* Wox = (const float*)d_in[7];
    const float* Woh = (const float*)d_in[8];
    const float* Wph = (const float*)d_in[9];
    const float* bf  = (const float*)d_in[10];
    const float* bg  = (const float*)d_in[11];
    const float* bi  = (const float*)d_in[12];
    const float* bo  = (const float*)d_in[13];
    const float* bp  = (const float*)d_in[14];
    float* out = (float*)d_out;

    cudaFuncSetAttribute(lstm_persistent_kernel,
                         cudaFuncAttributeMaxDynamicSharedMemorySize, SMEM_BYTES);

    init_kernel<<<(BATCH * HID + 255) / 256, 256>>>();

    size_t packN = (size_t)KTOT * NG;
    pack_kernel<<<(unsigned)((packN + 255) / 256), 256>>>(Wfx, Wfh, Wgx, Wgh,
                                                          Wix, Wih, Wox, Woh,
                                                          bf, bg, bi, bo);

    transpose_kernel<<<dim3(TSEQ / 32, (BATCH * DIN) / 32), dim3(32, 8)>>>(x);

    lstm_persistent_kernel<<<NBLK, 256, SMEM_BYTES>>>();

    head_kernel<<<BATCH, 256>>>(Wph, bp, out);
}

// round 11
// speedup vs baseline: 2.9662x; 2.9662x over previous
#include <cuda_runtime.h>
#include <mma.h>
#include <math.h>
#include <cstdint>
#include <cuda_fp16.h>

using namespace nvcuda;

#define BATCH 256
#define DIN   512
#define TSEQ  512
#define HID   1024
#define NG    4096
#define KTOT  1536
#define NCLS  1000

#define NBLK  128       // persistent blocks, one per SM, 32 gate-cols each
#define NB    32
#define WLDH  1544      // sW column stride in halves (3088 B, 16B multiple)
#define KC    32        // k-chunk per pipeline stage (2 fp16 k-steps)
#define NKIT  (KTOT / KC)   // 48
#define ALDH  40            // A stage row stride in halves (80 B, 16B multiple)
#define AWSZ  (32 * ALDH)   // per-warp A stage: 1280 halves = 2560 B

// SMEM layout (bytes)
#define OFF_W    0
#define W_BYTES  (NB * WLDH * 2)            // 98,816
#define OFF_A    W_BYTES
#define A_BYTES  (8 * 2 * AWSZ * 2)         // 40,960
#define OFF_C    (OFF_A + A_BYTES)          // 139,776
#define C_BYTES  (8 * 32 * 32 * 4)          // 32,768  (ld=32 floats: 128 B, legal)
#define OFF_BIAS (OFF_C + C_BYTES)          // 172,544
#define SMEM_BYTES (OFF_BIAS + 128)         // 172,672  (< 227 KB)

// ---------------- static device scratch ----------------
__device__ __half g_xh[(size_t)TSEQ * BATCH * DIN];  // x transposed [T][B][D], fp16
__device__ __half g_Wh[(size_t)KTOT * NG];           // [Wh; Wx] gate-interleaved, fp16
__device__ float  g_bias[NG];
__device__ __half g_h[2][(size_t)BATCH * HID];       // double-buffered hidden state (fp16)
__device__ float  g_c[(size_t)BATCH * HID];          // cell state (fp32)
__device__ unsigned g_arrive;
__device__ unsigned g_release;

__device__ __forceinline__ unsigned ld_acquire(const unsigned* p) {
    unsigned v;
    asm volatile("ld.acquire.gpu.global.u32 %0, [%1];" : "=r"(v) : "l"(p));
    return v;
}
__device__ __forceinline__ void st_release(unsigned* p, unsigned v) {
    asm volatile("st.release.gpu.global.u32 [%0], %1;" :: "l"(p), "r"(v));
}
__device__ __forceinline__ void cp16(uint32_t dst, const void* src) {
    asm volatile("cp.async.cg.shared.global [%0], [%1], 16;\n" :: "r"(dst), "l"(src));
}
__device__ __forceinline__ void cp_commit() {
    asm volatile("cp.async.commit_group;\n");
}
template <int N>
__device__ __forceinline__ void cp_wait() {
    asm volatile("cp.async.wait_group %0;\n" :: "n"(N));
}

// ---------------- init ----------------
__global__ void init_kernel() {
    size_t i = blockIdx.x * (size_t)blockDim.x + threadIdx.x;
    if (i < (size_t)BATCH * HID) {
        g_h[0][i] = __float2half(0.0f);
        g_c[i]    = 0.0f;
    }
    if (i == 0) { g_arrive = 0u; g_release = 0u; }
}

// ---------------- pack weights: g_Wh[k][u*4+gate], gates (g,f,i,o), fp16 ----------------
__global__ void pack_kernel(const float* __restrict__ Wfx, const float* __restrict__ Wfh,
                            const float* __restrict__ Wgx, const float* __restrict__ Wgh,
                            const float* __restrict__ Wix, const float* __restrict__ Wih,
                            const float* __restrict__ Wox, const float* __restrict__ Woh,
                            const float* __restrict__ bf,  const float* __restrict__ bg,
                            const float* __restrict__ bi,  const float* __restrict__ bo) {
    size_t idx = blockIdx.x * (size_t)blockDim.x + threadIdx.x;
    size_t total = (size_t)KTOT * NG;
    if (idx >= total) return;
    int e = (int)(idx % NG);
    int k = (int)(idx / NG);
    int u = e >> 2;
    int gate = e & 3;
    float v;
    if (k < HID) {
        const float* W = (gate == 0) ? Wgh : (gate == 1) ? Wfh : (gate == 2) ? Wih : Woh;
        v = W[(size_t)k * HID + u];
    } else {
        int d = k - HID;
        const float* W = (gate == 0) ? Wgx : (gate == 1) ? Wfx : (gate == 2) ? Wix : Wox;
        v = W[(size_t)d * HID + u];
    }
    g_Wh[idx] = __float2half(v);
    if (idx < NG) {
        const float* b = (gate == 0) ? bg : (gate == 1) ? bf : (gate == 2) ? bi : bo;
        g_bias[e] = b[u];
    }
}

// ---------------- transpose x [B,D,T] -> xh [T][B*D], fp16 ----------------
__global__ void transpose_kernel(const float* __restrict__ x) {
    __shared__ float tile[32][33];
    int t0 = blockIdx.x * 32;
    int r0 = blockIdx.y * 32;
    int tx = threadIdx.x;
    int ty = threadIdx.y;     // blockDim = (32, 8)
#pragma unroll
    for (int i = 0; i < 32; i += 8)
        tile[ty + i][tx] = x[(size_t)(r0 + ty + i) * TSEQ + (t0 + tx)];
    __syncthreads();
#pragma unroll
    for (int i = 0; i < 32; i += 8)
        g_xh[(size_t)(t0 + ty + i) * (BATCH * DIN) + (r0 + tx)] = __float2half(tile[tx][ty + i]);
}

// ================= persistent LSTM kernel, fp16 MMA =================
// 128 blocks x 256 threads. Block owns gate-cols n0..n0+31 (units u0..u0+7);
// W slice (fp16) SMEM-resident for the whole run. 8 warps each own a 32-row
// batch slab; per-warp double-buffered cp.async A staging, no block barriers
// in the k-loop. m16n16k16 fp16 MMA, fp32 accum. Grid softbarrier per step.
__global__ void __launch_bounds__(256) lstm_persistent_kernel() {
    extern __shared__ char smem[];
    __half* sW    = reinterpret_cast<__half*>(smem + OFF_W);
    float*  sBias = reinterpret_cast<float*>(smem + OFF_BIAS);

    const int tid  = threadIdx.x;
    const int warp = tid >> 5;
    const int lane = tid & 31;
    const int n0   = blockIdx.x * NB;
    const int m0   = warp * 32;               // this warp's batch rows
    __half* sA = reinterpret_cast<__half*>(smem + OFF_A) + warp * (2 * AWSZ);
    float*  sC = reinterpret_cast<float*>(smem + OFF_C) + warp * (32 * 32);

    uint32_t sA_base;
    {
        void* p = (void*)sA;
        asm("{ .reg .u64 tt; cvta.to.shared.u64 tt, %1; cvt.u32.u64 %0, tt; }"
            : "=r"(sA_base) : "l"(p));
    }

    // ---- one-time: W slice into SMEM: sW[n][k] = g_Wh[k][n0+n] ----
    for (int idx = tid; idx < KTOT * NB; idx += 256) {
        int k = idx >> 5;
        int n = idx & 31;
        sW[n * WLDH + k] = g_Wh[(size_t)k * NG + n0 + n];
    }
    if (tid < NB) sBias[tid] = g_bias[n0 + tid];

    const int eu   = lane & 7;                // epilogue unit 0..7
    const int ersb = lane >> 3;               // epilogue row sub 0..3
    const int u0   = n0 >> 2;
    __syncthreads();
    const float bias_g = sBias[eu * 4 + 0];
    const float bias_f = sBias[eu * 4 + 1];
    const float bias_i = sBias[eu * 4 + 2];
    const float bias_o = sBias[eu * 4 + 3];

    for (int t = 0; t < TSEQ; ++t) {
        const __half* __restrict__ hin  = g_h[t & 1];
        __half*       __restrict__ hout = g_h[(t + 1) & 1];
        const __half* __restrict__ xTt  = g_xh + (size_t)t * (BATCH * DIN);

        // per-warp stage: 32 rows x KC halves, 4 cp.async(16B) per lane
        auto stage = [&](int s, int kc) {
            const __half* srcbase;
            int rstride;
            if (kc < HID) { srcbase = hin + (size_t)m0 * HID + kc;         rstride = HID; }
            else          { srcbase = xTt + (size_t)m0 * DIN + (kc - HID); rstride = DIN; }
            uint32_t dst0 = sA_base + (uint32_t)(s * AWSZ) * 2u;
#pragma unroll
            for (int j = 0; j < 4; ++j) {
                int idx = j * 32 + lane;      // 128 x 16B
                int row = idx >> 2;
                int q   = idx & 3;
                cp16(dst0 + (uint32_t)(row * ALDH + q * 8) * 2u,
                     srcbase + (size_t)row * rstride + q * 8);
            }
            cp_commit();
        };

        wmma::fragment<wmma::accumulator, 16, 16, 16, float> acc[2][2];
#pragma unroll
        for (int am = 0; am < 2; ++am)
#pragma unroll
            for (int bn = 0; bn < 2; ++bn)
                wmma::fill_fragment(acc[am][bn], 0.0f);

        stage(0, 0);
        stage(1, KC);

        for (int it = 0; it < NKIT; ++it) {
            cp_wait<1>();
            __syncwarp();
            const int s = it & 1;
            const __half* cA = sA + s * AWSZ;
            const int kc = it * KC;

#pragma unroll
            for (int kk = 0; kk < KC; kk += 16) {
                wmma::fragment<wmma::matrix_a, 16, 16, 16, __half, wmma::row_major> af[2];
                wmma::fragment<wmma::matrix_b, 16, 16, 16, __half, wmma::col_major> bfr[2];
#pragma unroll
                for (int am = 0; am < 2; ++am)
                    wmma::load_matrix_sync(af[am], cA + (am * 16) * ALDH + kk, ALDH);
#pragma unroll
                for (int bn = 0; bn < 2; ++bn)
                    wmma::load_matrix_sync(bfr[bn], sW + (bn * 16) * WLDH + kc + kk, WLDH);
#pragma unroll
                for (int am = 0; am < 2; ++am)
#pragma unroll
                    for (int bn = 0; bn < 2; ++bn)
                        wmma::mma_sync(acc[am][bn], af[am], bfr[bn], acc[am][bn]);
            }

            // prefetch chunk it+2 into the stage just consumed
            if (it + 2 < NKIT) stage(s, (it + 2) * KC);
            else               cp_commit();   // keep group count consistent
        }
        cp_wait<0>();
        __syncwarp();

        // ---- epilogue (warp-local): C 32x32 (ld=32, 128 B) -> 8 units x 32 rows ----
#pragma unroll
        for (int am = 0; am < 2; ++am)
#pragma unroll
            for (int bn = 0; bn < 2; ++bn)
                wmma::store_matrix_sync(sC + (am * 16) * 32 + bn * 16,
                                        acc[am][bn], 32, wmma::mem_row_major);
        __syncwarp();

#pragma unroll
        for (int j = 0; j < 8; ++j) {
            int r = j * 4 + ersb;             // 0..31
            float gg = tanhf(sC[r * 32 + eu * 4 + 0] + bias_g);
            float ff = tanhf(sC[r * 32 + eu * 4 + 1] + bias_f);
            float ii = tanhf(sC[r * 32 + eu * 4 + 2] + bias_i);
            float oo = tanhf(sC[r * 32 + eu * 4 + 3] + bias_o);
            size_t cidx = (size_t)(m0 + r) * HID + (u0 + eu);
            float c = gg * ii + g_c[cidx] * ff;
            g_c[cidx]  = c;
            hout[cidx] = __float2half(tanhf(c) * oo);
        }

        // ---- grid softbarrier ----
        __threadfence();
        __syncthreads();
        if (tid == 0) {
            unsigned cnt    = atomicAdd(&g_arrive, 1u) + 1u;
            unsigned target = (unsigned)NBLK * (unsigned)(t + 1);
            if (cnt == target) {
                __threadfence();
                st_release(&g_release, (unsigned)(t + 1));
            } else {
                while (ld_acquire(&g_release) < (unsigned)(t + 1)) { }
            }
        }
        __syncthreads();
    }
}

// ---------------- head: softmax(h @ W_ph + b_p) ----------------
__global__ void __launch_bounds__(256) head_kernel(const float* __restrict__ Wph,
                                                   const float* __restrict__ bp,
                                                   float* __restrict__ out) {
    __shared__ float hs[HID];
    __shared__ float lg[NCLS];
    __shared__ float red[256];
    int b   = blockIdx.x;
    int tid = threadIdx.x;
    const __half* h = g_h[0];   // after 512 steps, final h lives in buffer 0

    for (int i = tid; i < HID; i += 256)
        hs[i] = __half2float(h[(size_t)b * HID + i]);
    __syncthreads();

    for (int c = tid; c < NCLS; c += 256) {
        float acc = bp[c];
#pragma unroll 8
        for (int k = 0; k < HID; ++k)
            acc += hs[k] * Wph[(size_t)k * NCLS + c];
        lg[c] = acc;
    }
    __syncthreads();

    float m = -1e30f;
    for (int c = tid; c < NCLS; c += 256) m = fmaxf(m, lg[c]);
    red[tid] = m;
    __syncthreads();
    for (int s = 128; s > 0; s >>= 1) {
        if (tid < s) red[tid] = fmaxf(red[tid], red[tid + s]);
        __syncthreads();
    }
    m = red[0];
    __syncthreads();

    float sum = 0.0f;
    for (int c = tid; c < NCLS; c += 256) {
        float ex = expf(lg[c] - m);
        lg[c] = ex;
        sum += ex;
    }
    red[tid] = sum;
    __syncthreads();
    for (int s = 128; s > 0; s >>= 1) {
        if (tid < s) red[tid] += red[tid + s];
        __syncthreads();
    }
    float inv = 1.0f / red[0];
    for (int c = tid; c < NCLS; c += 256)
        out[(size_t)b * NCLS + c] = lg[c] * inv;
}

// ---------------- launch ----------------
extern "C" void kernel_launch(void* const* d_in, const int* in_sizes, int n_in,
                              void* d_out, int out_size) {
    (void)in_sizes; (void)n_in; (void)out_size;
    const float* x   = (const float*)d_in[0];
    const float* Wfx = (const float*)d_in[1];
    const float* Wfh = (const float*)d_in[2];
    const float* Wgx = (const float*)d_in[3];
    const float* Wgh = (const float*)d_in[4];
    const float* Wix = (const float*)d_in[5];
    const float* Wih = (const float*)d_in[6];
    const float* Wox = (const float*)d_in[7];
    const float* Woh = (const float*)d_in[8];
    const float* Wph = (const float*)d_in[9];
    const float* bf  = (const float*)d_in[10];
    const float* bg  = (const float*)d_in[11];
    const float* bi  = (const float*)d_in[12];
    const float* bo  = (const float*)d_in[13];
    const float* bp  = (const float*)d_in[14];
    float* out = (float*)d_out;

    cudaFuncSetAttribute(lstm_persistent_kernel,
                         cudaFuncAttributeMaxDynamicSharedMemorySize, SMEM_BYTES);

    init_kernel<<<(BATCH * HID + 255) / 256, 256>>>();

    size_t packN = (size_t)KTOT * NG;
    pack_kernel<<<(unsigned)((packN + 255) / 256), 256>>>(Wfx, Wfh, Wgx, Wgh,
                                                          Wix, Wih, Wox, Woh,
                                                          bf, bg, bi, bo);

    transpose_kernel<<<dim3(TSEQ / 32, (BATCH * DIN) / 32), dim3(32, 8)>>>(x);

    lstm_persistent_kernel<<<NBLK, 256, SMEM_BYTES>>>();

    head_kernel<<<BATCH, 256>>>(Wph, bp, out);
}

// round 12
// speedup vs baseline: 3.4553x; 1.1649x over previous
#include <cuda_runtime.h>
#include <mma.h>
#include <math.h>
#include <cstdint>
#include <cuda_fp16.h>

using namespace nvcuda;

#define BATCH 256
#define DIN   512
#define TSEQ  512
#define HID   1024
#define NG    4096
#define KTOT  1536
#define NCLS  1000

#define NBLK  128       // persistent blocks, one per SM, 32 gate-cols each
#define NB    32
#define NWARP 16
#define WROWS 16        // batch rows per warp
#define WLDH  1544      // sW column stride in halves (3088 B, 16B multiple)
#define KC    32        // k-chunk per pipeline stage (2 fp16 k-steps)
#define NKIT  (KTOT / KC)   // 48
#define NSTG  3             // A pipeline stages per warp
#define ALDH  40            // A stage row stride in halves (80 B, 16B multiple)
#define AWSZ  (WROWS * ALDH)   // per-warp A stage: 640 halves = 1280 B

// SMEM layout (bytes)
#define OFF_W    0
#define W_BYTES  (NB * WLDH * 2)                  // 98,816
#define OFF_A    W_BYTES
#define A_BYTES  (NWARP * NSTG * AWSZ * 2)        // 61,440
#define OFF_C    (OFF_A + A_BYTES)                // 160,256
#define C_BYTES  (NWARP * WROWS * 32 * 4)         // 32,768 (ld=32 floats: 128 B, legal)
#define OFF_BIAS (OFF_C + C_BYTES)                // 193,024
#define SMEM_BYTES (OFF_BIAS + 128)               // 193,152  (< 227 KB)

// ---------------- static device scratch ----------------
__device__ __half g_xh[(size_t)TSEQ * BATCH * DIN];  // x transposed [T][B][D], fp16
__device__ __half g_Wh[(size_t)KTOT * NG];           // [Wh; Wx] gate-interleaved, fp16
__device__ float  g_bias[NG];
__device__ __half g_h[2][(size_t)BATCH * HID];       // double-buffered hidden state (fp16)
__device__ float  g_c[(size_t)BATCH * HID];          // cell state (fp32)
__device__ unsigned g_arrive;
__device__ unsigned g_release;

__device__ __forceinline__ unsigned ld_acquire(const unsigned* p) {
    unsigned v;
    asm volatile("ld.acquire.gpu.global.u32 %0, [%1];" : "=r"(v) : "l"(p));
    return v;
}
__device__ __forceinline__ void st_release(unsigned* p, unsigned v) {
    asm volatile("st.release.gpu.global.u32 [%0], %1;" :: "l"(p), "r"(v));
}
__device__ __forceinline__ void cp16(uint32_t dst, const void* src) {
    asm volatile("cp.async.cg.shared.global [%0], [%1], 16;\n" :: "r"(dst), "l"(src));
}
__device__ __forceinline__ void cp_commit() {
    asm volatile("cp.async.commit_group;\n");
}
template <int N>
__device__ __forceinline__ void cp_wait() {
    asm volatile("cp.async.wait_group %0;\n" :: "n"(N));
}

// ---------------- init ----------------
__global__ void init_kernel() {
    size_t i = blockIdx.x * (size_t)blockDim.x + threadIdx.x;
    if (i < (size_t)BATCH * HID) {
        g_h[0][i] = __float2half(0.0f);
        g_c[i]    = 0.0f;
    }
    if (i == 0) { g_arrive = 0u; g_release = 0u; }
}

// ---------------- pack weights: g_Wh[k][u*4+gate], gates (g,f,i,o), fp16 ----------------
__global__ void pack_kernel(const float* __restrict__ Wfx, const float* __restrict__ Wfh,
                            const float* __restrict__ Wgx, const float* __restrict__ Wgh,
                            const float* __restrict__ Wix, const float* __restrict__ Wih,
                            const float* __restrict__ Wox, const float* __restrict__ Woh,
                            const float* __restrict__ bf,  const float* __restrict__ bg,
                            const float* __restrict__ bi,  const float* __restrict__ bo) {
    size_t idx = blockIdx.x * (size_t)blockDim.x + threadIdx.x;
    size_t total = (size_t)KTOT * NG;
    if (idx >= total) return;
    int e = (int)(idx % NG);
    int k = (int)(idx / NG);
    int u = e >> 2;
    int gate = e & 3;
    float v;
    if (k < HID) {
        const float* W = (gate == 0) ? Wgh : (gate == 1) ? Wfh : (gate == 2) ? Wih : Woh;
        v = W[(size_t)k * HID + u];
    } else {
        int d = k - HID;
        const float* W = (gate == 0) ? Wgx : (gate == 1) ? Wfx : (gate == 2) ? Wix : Wox;
        v = W[(size_t)d * HID + u];
    }
    g_Wh[idx] = __float2half(v);
    if (idx < NG) {
        const float* b = (gate == 0) ? bg : (gate == 1) ? bf : (gate == 2) ? bi : bo;
        g_bias[e] = b[u];
    }
}

// ---------------- transpose x [B,D,T] -> xh [T][B*D], fp16 ----------------
__global__ void transpose_kernel(const float* __restrict__ x) {
    __shared__ float tile[32][33];
    int t0 = blockIdx.x * 32;
    int r0 = blockIdx.y * 32;
    int tx = threadIdx.x;
    int ty = threadIdx.y;     // blockDim = (32, 8)
#pragma unroll
    for (int i = 0; i < 32; i += 8)
        tile[ty + i][tx] = x[(size_t)(r0 + ty + i) * TSEQ + (t0 + tx)];
    __syncthreads();
#pragma unroll
    for (int i = 0; i < 32; i += 8)
        g_xh[(size_t)(t0 + ty + i) * (BATCH * DIN) + (r0 + tx)] = __float2half(tile[tx][ty + i]);
}

// ================= persistent LSTM kernel, fp16 MMA, 16 warps =================
// 128 blocks x 512 threads. Block owns gate-cols n0..n0+31 (units u0..u0+7);
// W slice (fp16) SMEM-resident for the whole run. 16 warps each own a 16-row
// batch slab; per-warp 3-stage cp.async A pipeline, no block barriers in the
// k-loop. m16n16k16 fp16 MMA, fp32 accum. Grid softbarrier per step.
__global__ void __launch_bounds__(512) lstm_persistent_kernel() {
    extern __shared__ char smem[];
    __half* sW    = reinterpret_cast<__half*>(smem + OFF_W);
    float*  sBias = reinterpret_cast<float*>(smem + OFF_BIAS);

    const int tid  = threadIdx.x;
    const int warp = tid >> 5;
    const int lane = tid & 31;
    const int n0   = blockIdx.x * NB;
    const int m0   = warp * WROWS;            // this warp's batch rows
    __half* sA = reinterpret_cast<__half*>(smem + OFF_A) + warp * (NSTG * AWSZ);
    float*  sC = reinterpret_cast<float*>(smem + OFF_C) + warp * (WROWS * 32);

    uint32_t sA_base;
    {
        void* p = (void*)sA;
        asm("{ .reg .u64 tt; cvta.to.shared.u64 tt, %1; cvt.u32.u64 %0, tt; }"
            : "=r"(sA_base) : "l"(p));
    }

    // ---- one-time: W slice into SMEM: sW[n][k] = g_Wh[k][n0+n] ----
    for (int idx = tid; idx < KTOT * NB; idx += 512) {
        int k = idx >> 5;
        int n = idx & 31;
        sW[n * WLDH + k] = g_Wh[(size_t)k * NG + n0 + n];
    }
    if (tid < NB) sBias[tid] = g_bias[n0 + tid];

    const int eu   = lane & 7;                // epilogue unit 0..7
    const int ersb = lane >> 3;               // epilogue row sub 0..3
    const int u0   = n0 >> 2;
    __syncthreads();
    const float bias_g = sBias[eu * 4 + 0];
    const float bias_f = sBias[eu * 4 + 1];
    const float bias_i = sBias[eu * 4 + 2];
    const float bias_o = sBias[eu * 4 + 3];

    for (int t = 0; t < TSEQ; ++t) {
        const __half* __restrict__ hin  = g_h[t & 1];
        __half*       __restrict__ hout = g_h[(t + 1) & 1];
        const __half* __restrict__ xTt  = g_xh + (size_t)t * (BATCH * DIN);

        // per-warp stage: 16 rows x KC halves, 2 cp.async(16B) per lane
        auto stage = [&](int s, int kc) {
            const __half* srcbase;
            int rstride;
            if (kc < HID) { srcbase = hin + (size_t)m0 * HID + kc;         rstride = HID; }
            else          { srcbase = xTt + (size_t)m0 * DIN + (kc - HID); rstride = DIN; }
            uint32_t dst0 = sA_base + (uint32_t)(s * AWSZ) * 2u;
#pragma unroll
            for (int j = 0; j < 2; ++j) {
                int idx = j * 32 + lane;      // 64 x 16B
                int row = idx >> 2;
                int q   = idx & 3;
                cp16(dst0 + (uint32_t)(row * ALDH + q * 8) * 2u,
                     srcbase + (size_t)row * rstride + q * 8);
            }
            cp_commit();
        };

        wmma::fragment<wmma::accumulator, 16, 16, 16, float> acc[2];
        wmma::fill_fragment(acc[0], 0.0f);
        wmma::fill_fragment(acc[1], 0.0f);

        stage(0, 0);
        stage(1, KC);
        stage(2, 2 * KC);

        for (int it = 0; it < NKIT; ++it) {
            cp_wait<2>();
            __syncwarp();
            const int s = it % NSTG;
            const __half* cA = sA + s * AWSZ;
            const int kc = it * KC;

#pragma unroll
            for (int kk = 0; kk < KC; kk += 16) {
                wmma::fragment<wmma::matrix_a, 16, 16, 16, __half, wmma::row_major> af;
                wmma::fragment<wmma::matrix_b, 16, 16, 16, __half, wmma::col_major> bfr[2];
                wmma::load_matrix_sync(af, cA + kk, ALDH);
#pragma unroll
                for (int bn = 0; bn < 2; ++bn)
                    wmma::load_matrix_sync(bfr[bn], sW + (bn * 16) * WLDH + kc + kk, WLDH);
#pragma unroll
                for (int bn = 0; bn < 2; ++bn)
                    wmma::mma_sync(acc[bn], af, bfr[bn], acc[bn]);
            }

            // prefetch chunk it+NSTG into the stage just consumed
            if (it + NSTG < NKIT) stage(s, (it + NSTG) * KC);
            else                  cp_commit();   // keep group count consistent
        }
        cp_wait<0>();
        __syncwarp();

        // ---- epilogue (warp-local): C 16x32 (ld=32, 128 B) -> 8 units x 16 rows ----
#pragma unroll
        for (int bn = 0; bn < 2; ++bn)
            wmma::store_matrix_sync(sC + bn * 16, acc[bn], 32, wmma::mem_row_major);
        __syncwarp();

#pragma unroll
        for (int j = 0; j < 4; ++j) {
            int r = j * 4 + ersb;             // 0..15
            float gg = tanhf(sC[r * 32 + eu * 4 + 0] + bias_g);
            float ff = tanhf(sC[r * 32 + eu * 4 + 1] + bias_f);
            float ii = tanhf(sC[r * 32 + eu * 4 + 2] + bias_i);
            float oo = tanhf(sC[r * 32 + eu * 4 + 3] + bias_o);
            size_t cidx = (size_t)(m0 + r) * HID + (u0 + eu);
            float c = gg * ii + g_c[cidx] * ff;
            g_c[cidx]  = c;
            hout[cidx] = __float2half(tanhf(c) * oo);
        }

        // ---- grid softbarrier ----
        __threadfence();
        __syncthreads();
        if (tid == 0) {
            unsigned cnt    = atomicAdd(&g_arrive, 1u) + 1u;
            unsigned target = (unsigned)NBLK * (unsigned)(t + 1);
            if (cnt == target) {
                __threadfence();
                st_release(&g_release, (unsigned)(t + 1));
            } else {
                while (ld_acquire(&g_release) < (unsigned)(t + 1)) { }
            }
        }
        __syncthreads();
    }
}

// ---------------- head: softmax(h @ W_ph + b_p) ----------------
__global__ void __launch_bounds__(256) head_kernel(const float* __restrict__ Wph,
                                                   const float* __restrict__ bp,
                                                   float* __restrict__ out) {
    __shared__ float hs[HID];
    __shared__ float lg[NCLS];
    __shared__ float red[256];
    int b   = blockIdx.x;
    int tid = threadIdx.x;
    const __half* h = g_h[0];   // after 512 steps, final h lives in buffer 0

    for (int i = tid; i < HID; i += 256)
        hs[i] = __half2float(h[(size_t)b * HID + i]);
    __syncthreads();

    for (int c = tid; c < NCLS; c += 256) {
        float acc = bp[c];
#pragma unroll 8
        for (int k = 0; k < HID; ++k)
            acc += hs[k] * Wph[(size_t)k * NCLS + c];
        lg[c] = acc;
    }
    __syncthreads();

    float m = -1e30f;
    for (int c = tid; c < NCLS; c += 256) m = fmaxf(m, lg[c]);
    red[tid] = m;
    __syncthreads();
    for (int s = 128; s > 0; s >>= 1) {
        if (tid < s) red[tid] = fmaxf(red[tid], red[tid + s]);
        __syncthreads();
    }
    m = red[0];
    __syncthreads();

    float sum = 0.0f;
    for (int c = tid; c < NCLS; c += 256) {
        float ex = expf(lg[c] - m);
        lg[c] = ex;
        sum += ex;
    }
    red[tid] = sum;
    __syncthreads();
    for (int s = 128; s > 0; s >>= 1) {
        if (tid < s) red[tid] += red[tid + s];
        __syncthreads();
    }
    float inv = 1.0f / red[0];
    for (int c = tid; c < NCLS; c += 256)
        out[(size_t)b * NCLS + c] = lg[c] * inv;
}

// ---------------- launch ----------------
extern "C" void kernel_launch(void* const* d_in, const int* in_sizes, int n_in,
                              void* d_out, int out_size) {
    (void)in_sizes; (void)n_in; (void)out_size;
    const float* x   = (const float*)d_in[0];
    const float* Wfx = (const float*)d_in[1];
    const float* Wfh = (const float*)d_in[2];
    const float* Wgx = (const float*)d_in[3];
    const float* Wgh = (const float*)d_in[4];
    const float* Wix = (const float*)d_in[5];
    const float* Wih = (const float*)d_in[6];
    const float* Wox = (const float*)d_in[7];
    const float* Woh = (const float*)d_in[8];
    const float* Wph = (const float*)d_in[9];
    const float* bf  = (const float*)d_in[10];
    const float* bg  = (const float*)d_in[11];
    const float* bi  = (const float*)d_in[12];
    const float* bo  = (const float*)d_in[13];
    const float* bp  = (const float*)d_in[14];
    float* out = (float*)d_out;

    cudaFuncSetAttribute(lstm_persistent_kernel,
                         cudaFuncAttributeMaxDynamicSharedMemorySize, SMEM_BYTES);

    init_kernel<<<(BATCH * HID + 255) / 256, 256>>>();

    size_t packN = (size_t)KTOT * NG;
    pack_kernel<<<(unsigned)((packN + 255) / 256), 256>>>(Wfx, Wfh, Wgx, Wgh,
                                                          Wix, Wih, Wox, Woh,
                                                          bf, bg, bi, bo);

    transpose_kernel<<<dim3(TSEQ / 32, (BATCH * DIN) / 32), dim3(32, 8)>>>(x);

    lstm_persistent_kernel<<<NBLK, 512, SMEM_BYTES>>>();

    head_kernel<<<BATCH, 256>>>(Wph, bp, out);
}